// round 14
// baseline (speedup 1.0000x reference)
#include <cuda_runtime.h>
#include <cstdint>

// ---------------- constants (STATS are fixed) ----------------
#define S1 (3.5f/255.0f)   // conv1 stat (-0.5, 3.0)
#define ZP1 36.0f          // trunc(0.5/S1)
#define INV_S2 42.5f       // 255/6  (exact)
#define INV_S3 31.875f     // 255/8  (exact)
#define INV_S4 25.5f       // 255/10 (exact)
#define S4 (10.0f/255.0f)
#define S2C (6.0f/255.0f)
#define S3C (8.0f/255.0f)

#define BATCH 4096
#define C2_CPAD 52

// ---------------- device scratch ----------------
// statically armed for the first (correctness) call; fc2 re-arms for the next call
__device__ unsigned g_mmkey[12] = {0xFFFFFFFFu,0u, 0xFFFFFFFFu,0u, 0xFFFFFFFFu,0u,
                                   0xFFFFFFFFu,0u, 0xFFFFFFFFu,0u, 0xFFFFFFFFu,0u};
__device__ __align__(16) unsigned g_w1lo[5*20];
__device__ __align__(16) unsigned g_w1hi[5*20];
__device__ float g_c1c[20];                              // conv1 const, pre-scaled by INV_S2
__device__ __align__(16) unsigned g_w2q[5*25*C2_CPAD];  // conv2 wq packed: [p][r=ky*5+kx][c]
__device__ float g_b2eff[C2_CPAD];
__device__ __align__(16) unsigned g_fc1q[200*512];      // fc1 wq packed: [kp=200][n pad 512]
__device__ float g_b3eff[512];
__device__ __align__(16) unsigned char g_act1[BATCH*12*5*12*4];
__device__ __align__(16) unsigned char g_act2[BATCH*50*4*4];
__device__ int g_rowsum[BATCH];
__device__ __align__(16) unsigned char g_xq[BATCH*500];  // fc1 output q-values (u8)

// ---------------- helpers ----------------
__device__ __forceinline__ float clip255(float v){ return fminf(fmaxf(v, 0.0f), 255.0f); }
__device__ __forceinline__ unsigned f2key(float f){
    unsigned u = __float_as_uint(f);
    return (u & 0x80000000u) ? ~u : (u | 0x80000000u);
}
__device__ __forceinline__ float key2f(unsigned k){
    return __uint_as_float((k & 0x80000000u) ? (k & 0x7fffffffu) : ~k);
}
__device__ __forceinline__ void get_sz(int t, float& scale, float& zp){
    float mn = key2f(g_mmkey[2*t]);
    float mx = key2f(g_mmkey[2*t+1]);
    scale = (mx - mn) / 255.0f;
    zp = truncf(clip255(-mn / scale));
}
__device__ __forceinline__ void get_szi(int t, float& inv, float& zp){
    float mn = key2f(g_mmkey[2*t]);
    float mx = key2f(g_mmkey[2*t+1]);
    float scale = (mx - mn) / 255.0f;
    inv = 255.0f / (mx - mn);
    zp = truncf(clip255(-mn / scale));
}
__device__ __forceinline__ float qroundi(float v, float inv, float zp){
    return rintf(clip255(zp + v * inv));
}

// ---------------- min/max over 6 param tensors ----------------
__global__ void minmax_kernel(const float* __restrict__ c1w, const float* __restrict__ c1b,
                              const float* __restrict__ c2w, const float* __restrict__ c2b,
                              const float* __restrict__ f1w, const float* __restrict__ f1b){
    __shared__ unsigned smn[256], smx[256];
    int b = blockIdx.x, tid = threadIdx.x;
    const float* p; int n, t, sub, nb;
    if (b < 64)      { t = 4; p = f1w; n = 400000; sub = b;      nb = 64; }
    else if (b < 68) { t = 2; p = c2w; n = 25000;  sub = b - 64; nb = 4;  }
    else if (b == 68){ t = 0; p = c1w; n = 500;    sub = 0;      nb = 1;  }
    else if (b == 69){ t = 1; p = c1b; n = 20;     sub = 0;      nb = 1;  }
    else if (b == 70){ t = 3; p = c2b; n = 50;     sub = 0;      nb = 1;  }
    else             { t = 5; p = f1b; n = 500;    sub = 0;      nb = 1;  }

    unsigned lmin = 0xFFFFFFFFu, lmax = 0u;
    for (int i = sub*256 + tid; i < n; i += nb*256){
        unsigned k = f2key(p[i]);
        lmin = min(lmin, k); lmax = max(lmax, k);
    }
    smn[tid] = lmin; smx[tid] = lmax;
    __syncthreads();
    for (int s = 128; s; s >>= 1){
        if (tid < s){
            smn[tid] = min(smn[tid], smn[tid+s]);
            smx[tid] = max(smx[tid], smx[tid+s]);
        }
        __syncthreads();
    }
    if (tid == 0){
        atomicMin(&g_mmkey[2*t],   smn[0]);
        atomicMax(&g_mmkey[2*t+1], smx[0]);
    }
}

// ---------------- build packed weights / constants ----------------
__global__ void effs_kernel(const float* __restrict__ c1w, const float* __restrict__ c1b,
                            const float* __restrict__ c2w, const float* __restrict__ c2b,
                            const float* __restrict__ f1w, const float* __restrict__ f1b){
    int idx = blockIdx.x*blockDim.x + threadIdx.x;
    if (idx < 100){
        int ky = idx / 20, ch = idx % 20;
        float iv, z; get_szi(0, iv, z);
        unsigned lo = 0u;
        #pragma unroll
        for (int j = 0; j < 4; j++){
            unsigned wq = (unsigned)qroundi(c1w[ch*25 + ky*5 + j], iv, z);
            lo |= (wq & 0xffu) << (8*j);
        }
        g_w1lo[idx] = lo;
        g_w1hi[idx] = (unsigned)qroundi(c1w[ch*25 + ky*5 + 4], iv, z) & 0xffu;
    } else if (idx < 120){
        int ch = idx - 100;
        float iv, z; get_szi(0, iv, z);
        float s, zz; get_sz(0, s, zz);
        float wsum = 0.0f;
        for (int k = 0; k < 25; k++) wsum += qroundi(c1w[ch*25 + k], iv, z);
        float ivb, zb; get_szi(1, ivb, zb);
        float sb, zb2; get_sz(1, sb, zb2);
        float beff = sb * (qroundi(c1b[ch], ivb, zb) + zb);
        g_c1c[ch] = (beff + (S1 * s) * (900.0f * z - 36.0f * wsum)) * INV_S2;
    } else if (idx < 6620){                               // conv2 wq packed [p][r][c]
        int e = idx - 120;
        int p = e / (25*C2_CPAD), r = (e / C2_CPAD) % 25, c = e % C2_CPAD;
        unsigned pk = 0u;
        if (c < 50){
            float iv, z; get_szi(2, iv, z);
            #pragma unroll
            for (int j = 0; j < 4; j++){
                int ci = p*4 + j;
                unsigned wq = (unsigned)qroundi(c2w[c*500 + ci*25 + r], iv, z);
                pk |= (wq & 0xffu) << (8*j);
            }
        }
        g_w2q[e] = pk;
    } else if (idx < 6672){
        int c = idx - 6620;
        float val = 0.0f;
        if (c < 50){
            float s, z; get_sz(3, s, z);
            val = s * (qroundi(c2b[c], 255.0f/( (key2f(g_mmkey[7]) - key2f(g_mmkey[6])) ), z) + z);
        }
        g_b2eff[c] = val;
    } else if (idx < 109072){
        int e = idx - 6672;
        int kp = e / 512, n = e % 512;
        unsigned pk = 0u;
        if (n < 500){
            float iv, z; get_szi(4, iv, z);
            #pragma unroll
            for (int j = 0; j < 4; j++){
                int k = kp*4 + j;
                unsigned wq = (unsigned)qroundi(f1w[n*800 + k], iv, z);
                pk |= (wq & 0xffu) << (8*j);
            }
        }
        g_fc1q[e] = pk;
    } else if (idx < 109584){
        int n = idx - 109072;
        float val = 0.0f;
        if (n < 500){
            float iv, z; get_szi(5, iv, z);
            float s, zz; get_sz(5, s, zz);
            val = s * (qroundi(f1b[n], iv, z) + z);
        }
        g_b3eff[n] = val;
    }
}

// ---------------- conv1 via dp4a, fused integer pool + quant (2 images/block) ----------------
__global__ void __launch_bounds__(384, 3) conv1_kernel(const float* __restrict__ x){
    __shared__ unsigned q0u[2][28*8];
    __shared__ unsigned Wn[2][28*28];
    __shared__ unsigned Ps[2][24*24];
    __shared__ unsigned wlo_s[100], whi_s[100];
    __shared__ float cc_s[20];

    int imgbase = blockIdx.x * 2, tid = threadIdx.x;

    for (int i = tid; i < 448; i += 384){
        int im = i / 224, e = i % 224;
        int r = e / 8, c4 = e % 8;
        unsigned pk = 0u;
        if (c4 < 7){
            const float* xi = x + (imgbase + im)*784;
            #pragma unroll
            for (int j = 0; j < 4; j++){
                float v = xi[r*28 + c4*4 + j];
                unsigned q = (unsigned)rintf(clip255(ZP1 + v / S1));
                pk |= (q & 0xffu) << (8*j);
            }
        }
        q0u[im][r*8 + c4] = pk;
    }
    for (int i = tid; i < 100; i += 384){ wlo_s[i] = g_w1lo[i]; whi_s[i] = g_w1hi[i]; }
    if (tid < 20) cc_s[tid] = g_c1c[tid];
    __syncthreads();

    for (int i = tid; i < 1568; i += 384){
        int im = i / 784, e = i % 784;
        int r = e / 28, xx = e % 28;
        unsigned a = q0u[im][r*8 + (xx >> 2)];
        unsigned b = q0u[im][r*8 + (xx >> 2) + 1];
        Wn[im][e] = __funnelshift_r(a, b, 8*(xx & 3));
    }
    __syncthreads();

    for (int i = tid; i < 1152; i += 384){
        int im = i / 576, e = i % 576;
        int y = e / 24, xx = e % 24;
        unsigned s = 0;
        #pragma unroll
        for (int ky = 0; ky < 5; ky++){
            s = __dp4a(Wn[im][(y + ky)*28 + xx], 0x01010101u, s);
            s += (q0u[im][(y + ky)*8 + ((xx + 4) >> 2)] >> (8*((xx + 4) & 3))) & 0xffu;
        }
        Ps[im][e] = s;
    }
    __syncthreads();

    if (tid < 360){
        int rr = tid / 30;
        int t  = tid % 30;
        int cg = t / 6, xp = t % 6;
        int x0 = xp * 4;

        float s_w, z_w; get_sz(0, s_w, z_w);
        float Af = S1 * s_w * INV_S2;
        int zpi = (int)z_w;

        #pragma unroll 1
        for (int im = 0; im < 2; im++){
            unsigned acc[2][4][4] = {};

            #pragma unroll
            for (int ir = 0; ir < 6; ir++){
                const uint4* w4 = (const uint4*)&Wn[im][(2*rr + ir)*28 + x0];
                uint4 lo4 = w4[0], hi4 = w4[1];
                unsigned wn[8] = {lo4.x,lo4.y,lo4.z,lo4.w, hi4.x,hi4.y,hi4.z,hi4.w};
                #pragma unroll
                for (int row = 0; row < 2; row++){
                    int ky = ir - row;
                    if (ky >= 0 && ky <= 4){
                        uint4 wlo = *(const uint4*)&wlo_s[ky*20 + cg*4];
                        uint4 whi = *(const uint4*)&whi_s[ky*20 + cg*4];
                        #pragma unroll
                        for (int c = 0; c < 4; c++){
                            unsigned wl = wn[c], wh = wn[c + 4];
                            acc[row][c][0] = __dp4a(wl, wlo.x, acc[row][c][0]);
                            acc[row][c][1] = __dp4a(wl, wlo.y, acc[row][c][1]);
                            acc[row][c][2] = __dp4a(wl, wlo.z, acc[row][c][2]);
                            acc[row][c][3] = __dp4a(wl, wlo.w, acc[row][c][3]);
                            acc[row][c][0] = __dp4a(wh, whi.x, acc[row][c][0]);
                            acc[row][c][1] = __dp4a(wh, whi.y, acc[row][c][1]);
                            acc[row][c][2] = __dp4a(wh, whi.z, acc[row][c][2]);
                            acc[row][c][3] = __dp4a(wh, whi.w, acc[row][c][3]);
                        }
                    }
                }
            }

            int ZP[2][4];
            #pragma unroll
            for (int rw = 0; rw < 2; rw++)
                #pragma unroll
                for (int cl = 0; cl < 4; cl++)
                    ZP[rw][cl] = zpi * (int)Ps[im][(2*rr + rw)*24 + x0 + cl];

            unsigned ow0 = 0u, ow1 = 0u;
            #pragma unroll
            for (int c = 0; c < 4; c++){
                float Cc = cc_s[cg*4 + c];
                #pragma unroll
                for (int px = 0; px < 2; px++){
                    int i0 = (int)acc[0][2*px    ][c] - ZP[0][2*px    ];
                    int i1 = (int)acc[0][2*px + 1][c] - ZP[0][2*px + 1];
                    int i2 = (int)acc[1][2*px    ][c] - ZP[1][2*px    ];
                    int i3 = (int)acc[1][2*px + 1][c] - ZP[1][2*px + 1];
                    int imx = max(max(i0, i1), max(i2, i3));
                    float q = rintf(fmaxf(Af*(float)imx + Cc, 0.0f));
                    unsigned qb = ((unsigned)q & 0xffu) << (8*c);
                    if (px == 0) ow0 |= qb; else ow1 |= qb;
                }
            }
            unsigned* dst = (unsigned*)g_act1 + (((imgbase + im)*12 + rr)*5 + cg)*12 + xp*2;
            dst[0] = ow0; dst[1] = ow1;
        }
    }
}

// ---------------- conv2: heterogeneous blocks — even bid = int8 mma, odd bid = dp4a ----------------
// Register-capped to 5 blocks/SM to restore mma-block density (round-13 fix).
#define CV2_XS   0                          // 5760 B  (2*720 u32)
#define CV2_SW   5760                       // 512 B   (2*64 u32)
#define CV2_BEFF 6272                       // 208 B
#define CV2_RSUM 6480                       // 16 B
#define CV2_Q2   6496                       // 6656 B  (2*52*64)
#define CV2_WB   13152                      // branch area
#define CV2_TOTAL (CV2_WB + 28672 + 512)    // mma: Bs 28672 + offA 512 -> 42336 B

__global__ void __launch_bounds__(256, 5) conv2_kernel(){
    __shared__ __align__(16) char smu[CV2_TOTAL];
    unsigned* Xs      = (unsigned*)(smu + CV2_XS);    // [li][y][p][x]
    unsigned* Sw      = (unsigned*)(smu + CV2_SW);    // [li][64]
    float*    beff_s  = (float*)(smu + CV2_BEFF);
    int*      rsum    = (int*)(smu + CV2_RSUM);
    unsigned char* q2 = (unsigned char*)(smu + CV2_Q2); // [li][ch pad52][8][8]
    unsigned* Bs      = (unsigned*)(smu + CV2_WB);    // mma: [g = r*5+p][56]
    int*      offA    = (int*)(smu + CV2_WB + 28672);
    unsigned* Wq_s    = (unsigned*)(smu + CV2_WB);    // dp4a: [p*25 + r][52]

    int tid = threadIdx.x;
    int bid = blockIdx.x;
    int imgbase = bid * 2;
    bool is_mma = (bid & 1) == 0;     // block-uniform

    // common: load act1 tiles
    {
        const uint4* xsrc = (const uint4*)(g_act1 + imgbase*2880);
        for (int i = tid; i < 360; i += 256) ((uint4*)Xs)[i] = xsrc[i];
    }
    if (is_mma){
        for (int i = tid; i < 128*14; i += 256){
            int g = i / 14, c4 = i % 14;
            uint4 v = make_uint4(0u,0u,0u,0u);
            if (g < 125 && c4 < 13){
                int r = g / 5, p = g % 5;
                v = *(const uint4*)&g_w2q[(p*25 + r)*C2_CPAD + c4*4];
            }
            ((uint4*)Bs)[g*14 + c4] = v;
        }
        if (tid < 128){
            int g = tid;
            int r = (g < 125) ? g/5 : 0, p = (g < 125) ? g%5 : 0;
            offA[tid] = (r/5)*60 + p*12 + (r%5);
        }
    } else {
        for (int i = tid; i < 1625; i += 256)
            ((uint4*)Wq_s)[i] = ((const uint4*)g_w2q)[i];
    }
    if (tid < C2_CPAD) beff_s[tid] = g_b2eff[tid];
    if (tid < 2) rsum[tid] = 0;
    __syncthreads();

    // common: window sums (for zp correction)
    if (tid < 128){
        int li = tid >> 6, pos = tid & 63;
        int oy = pos >> 3, ox = pos & 7;
        unsigned s = 0;
        for (int ky = 0; ky < 5; ky++)
            for (int p = 0; p < 5; p++){
                const unsigned* row = &Xs[li*720 + (oy + ky)*60 + p*12];
                #pragma unroll
                for (int kx = 0; kx < 5; kx++)
                    s = __dp4a(row[ox + kx], 0x01010101u, s);
            }
        Sw[tid] = s;
    }

    float s2w, z2w; get_sz(2, s2w, z2w);
    float S2s = S2C * s2w;
    int zp2 = (int)z2w;

    if (is_mma){
        // ---- tensor path (round-8 proven) ----
        int w = tid >> 5, l = tid & 31;
        int li = w >> 2, mtile = w & 3;
        int lr = l >> 2, lc = l & 3;
        int oy0 = mtile*2;
        int base0 = li*720 + oy0*60 + lr;
        int base1 = base0 + 60;

        int acc[7][4];
        #pragma unroll
        for (int t = 0; t < 7; t++)
            #pragma unroll
            for (int j = 0; j < 4; j++) acc[t][j] = 0;

        #pragma unroll 1
        for (int step = 0; step < 16; step++){
            int g0 = step*8 + lc;
            int g1 = g0 + 4;
            unsigned a0 = Xs[base0 + offA[g0]];
            unsigned a1 = Xs[base1 + offA[g0]];
            unsigned a2 = Xs[base0 + offA[g1]];
            unsigned a3 = Xs[base1 + offA[g1]];
            const unsigned* b0r = &Bs[g0*56 + lr];
            const unsigned* b1r = &Bs[g1*56 + lr];
            #pragma unroll
            for (int t = 0; t < 7; t++){
                unsigned b0 = b0r[t*8];
                unsigned b1 = b1r[t*8];
                asm volatile(
                    "mma.sync.aligned.m16n8k32.row.col.s32.u8.u8.s32 "
                    "{%0,%1,%2,%3}, {%4,%5,%6,%7}, {%8,%9}, {%0,%1,%2,%3};"
                    : "+r"(acc[t][0]), "+r"(acc[t][1]), "+r"(acc[t][2]), "+r"(acc[t][3])
                    : "r"(a0), "r"(a1), "r"(a2), "r"(a3), "r"(b0), "r"(b1));
            }
        }
        __syncthreads();   // block-uniform branch: legal

        #pragma unroll
        for (int half = 0; half < 2; half++){
            int oy = oy0 + half, ox = lr;
            int sw = (int)Sw[li*64 + oy*8 + ox];
            #pragma unroll
            for (int t = 0; t < 7; t++){
                #pragma unroll
                for (int j = 0; j < 2; j++){
                    int ch = t*8 + lc*2 + j;
                    if (ch < C2_CPAD){
                        int cval = acc[t][half*2 + j];
                        float val = S2s * (float)(cval - zp2*sw) + beff_s[ch];
                        float v = rintf(fmaxf(val * INV_S3, 0.0f));
                        q2[((li*C2_CPAD + ch)*8 + oy)*8 + ox] = (unsigned char)(unsigned)v;
                    }
                }
            }
        }
    } else {
        // ---- dp4a path (round-2 proven) ----
        int active = tid < 208;
        int li = 0, y = 0, cg = 0;
        unsigned acc[8][4];
        #pragma unroll
        for (int xx = 0; xx < 8; xx++)
            #pragma unroll
            for (int c = 0; c < 4; c++) acc[xx][c] = 0u;

        if (active){
            li = tid / 104;
            int t = tid % 104;
            y = t / 13; cg = t % 13;

            #pragma unroll 1
            for (int p = 0; p < 5; p++){
                #pragma unroll
                for (int ky = 0; ky < 5; ky++){
                    const uint4* xr4 = (const uint4*)&Xs[li*720 + (y + ky)*60 + p*12];
                    uint4 a0 = xr4[0], a1 = xr4[1], a2 = xr4[2];
                    unsigned xv[12] = {a0.x,a0.y,a0.z,a0.w, a1.x,a1.y,a1.z,a1.w, a2.x,a2.y,a2.z,a2.w};
                    #pragma unroll
                    for (int kx = 0; kx < 5; kx++){
                        uint4 wq = *(const uint4*)&Wq_s[(p*25 + ky*5 + kx)*C2_CPAD + cg*4];
                        #pragma unroll
                        for (int xx = 0; xx < 8; xx++){
                            unsigned xvv = xv[xx + kx];
                            acc[xx][0] = __dp4a(xvv, wq.x, acc[xx][0]);
                            acc[xx][1] = __dp4a(xvv, wq.y, acc[xx][1]);
                            acc[xx][2] = __dp4a(xvv, wq.z, acc[xx][2]);
                            acc[xx][3] = __dp4a(xvv, wq.w, acc[xx][3]);
                        }
                    }
                }
            }
        }
        __syncthreads();   // Sw visible

        if (active){
            #pragma unroll
            for (int c = 0; c < 4; c++){
                int ch = cg*4 + c;
                float beff = beff_s[ch];
                #pragma unroll
                for (int xx = 0; xx < 8; xx++){
                    int sw = (int)Sw[li*64 + y*8 + xx];
                    int idiff = (int)acc[xx][c] - zp2*sw;
                    float val = S2s * (float)idiff + beff;
                    float v = rintf(fmaxf(val * INV_S3, 0.0f));
                    q2[((li*C2_CPAD + ch)*8 + y)*8 + xx] = (unsigned char)(unsigned)v;
                }
            }
        }
    }
    __syncthreads();

    // common: pool 2x2 + per-image rowsum
    int lsum0 = 0, lsum1 = 0;
    for (int i = tid; i < 1600; i += 256){
        int im = i / 800, rest = i % 800;
        int ch = rest / 16, pr = (rest % 16) / 4, pc = rest % 4;
        const unsigned char* bp = q2 + ((im*C2_CPAD + ch)*8 + 2*pr)*8 + 2*pc;
        unsigned char m = max(max(bp[0], bp[1]), max(bp[8], bp[9]));
        g_act2[((imgbase + im)*50 + ch)*16 + pr*4 + pc] = m;
        if (im == 0) lsum0 += m; else lsum1 += m;
    }
    #pragma unroll
    for (int off = 16; off; off >>= 1){
        lsum0 += __shfl_down_sync(0xffffffffu, lsum0, off);
        lsum1 += __shfl_down_sync(0xffffffffu, lsum1, off);
    }
    if ((tid & 31) == 0){
        if (lsum0) atomicAdd(&rsum[0], lsum0);
        if (lsum1) atomicAdd(&rsum[1], lsum1);
    }
    __syncthreads();
    if (tid < 2) g_rowsum[imgbase + tid] = rsum[tid];
}

// ---------------- fc1 via int8 mma + quant; output u8 q-values ----------------
__global__ void __launch_bounds__(256) fc1_kernel(){
    __shared__ unsigned As[64*44];
    __shared__ unsigned Bs[40*72];

    int tid = threadIdx.x;
    int w = tid >> 5, l = tid & 31;
    int lr = l >> 2, lc = l & 3;
    int m0 = blockIdx.x * 64, n0 = blockIdx.y * 64;
    int wm = (w & 1) * 32;
    int wn = (w >> 1) * 16;

    int acc[2][2][4];
    #pragma unroll
    for (int mt = 0; mt < 2; mt++)
        #pragma unroll
        for (int nt = 0; nt < 2; nt++)
            #pragma unroll
            for (int j = 0; j < 4; j++) acc[mt][nt][j] = 0;

    const unsigned* Xg = (const unsigned*)g_act2;

    #pragma unroll 1
    for (int chunk = 0; chunk < 5; chunk++){
        for (int i = tid; i < 640; i += 256){
            int r = i / 10, c4 = i % 10;
            uint4 v = *(const uint4*)&Xg[(m0 + r)*200 + chunk*40 + c4*4];
            *(uint4*)&As[r*44 + c4*4] = v;
        }
        for (int i = tid; i < 640; i += 256){
            int kr = i / 16, c4 = i % 16;
            uint4 v = *(const uint4*)&g_fc1q[(chunk*40 + kr)*512 + n0 + c4*4];
            *(uint4*)&Bs[kr*72 + c4*4] = v;
        }
        __syncthreads();

        #pragma unroll
        for (int s = 0; s < 5; s++){
            int g = s*8;
            unsigned a[2][4];
            #pragma unroll
            for (int mt = 0; mt < 2; mt++){
                int r0 = wm + mt*16 + lr;
                a[mt][0] = As[r0*44 + g + lc];
                a[mt][1] = As[(r0 + 8)*44 + g + lc];
                a[mt][2] = As[r0*44 + g + 4 + lc];
                a[mt][3] = As[(r0 + 8)*44 + g + 4 + lc];
            }
            unsigned b[2][2];
            #pragma unroll
            for (int nt = 0; nt < 2; nt++){
                int nn = wn + nt*8 + lr;
                b[nt][0] = Bs[(g + lc)*72 + nn];
                b[nt][1] = Bs[(g + 4 + lc)*72 + nn];
            }
            #pragma unroll
            for (int mt = 0; mt < 2; mt++)
                #pragma unroll
                for (int nt = 0; nt < 2; nt++){
                    asm volatile(
                        "mma.sync.aligned.m16n8k32.row.col.s32.u8.u8.s32 "
                        "{%0,%1,%2,%3}, {%4,%5,%6,%7}, {%8,%9}, {%0,%1,%2,%3};"
                        : "+r"(acc[mt][nt][0]), "+r"(acc[mt][nt][1]),
                          "+r"(acc[mt][nt][2]), "+r"(acc[mt][nt][3])
                        : "r"(a[mt][0]), "r"(a[mt][1]), "r"(a[mt][2]), "r"(a[mt][3]),
                          "r"(b[nt][0]), "r"(b[nt][1]));
                }
        }
        __syncthreads();
    }

    float s3w, z3w; get_sz(4, s3w, z3w);
    float S3s = S3C * s3w;
    int zp3 = (int)z3w;

    #pragma unroll
    for (int mt = 0; mt < 2; mt++){
        int mr0 = m0 + wm + mt*16 + lr;
        int rs0 = g_rowsum[mr0];
        int rs1 = g_rowsum[mr0 + 8];
        #pragma unroll
        for (int nt = 0; nt < 2; nt++){
            int nb = n0 + wn + nt*8 + 2*lc;
            #pragma unroll
            for (int j = 0; j < 2; j++){
                int n = nb + j;
                if (n < 500){
                    float y0 = S3s * (float)(acc[mt][nt][j]     - zp3 * rs0) + g_b3eff[n];
                    float v0 = rintf(fmaxf(y0 * INV_S4, 0.0f));
                    g_xq[mr0*500 + n] = (unsigned char)((unsigned)v0 & 0xffu);
                    float y1 = S3s * (float)(acc[mt][nt][2 + j] - zp3 * rs1) + g_b3eff[n];
                    float v1 = rintf(fmaxf(y1 * INV_S4, 0.0f));
                    g_xq[(mr0 + 8)*500 + n] = (unsigned char)((unsigned)v1 & 0xffu);
                }
            }
        }
    }
}

// ---------------- fc2 + log_softmax (+ re-arm minmax keys for next run) ----------------
__global__ void __launch_bounds__(128) fc2_kernel(const float* __restrict__ w,
                                                  const float* __restrict__ bias,
                                                  float* __restrict__ out){
    __shared__ float ws[5000];
    __shared__ float bsh[10];
    int tid = threadIdx.x;

    if (blockIdx.x == 0 && tid < 12)
        g_mmkey[tid] = (tid & 1) ? 0u : 0xFFFFFFFFu;

    for (int i = tid; i < 5000; i += 128) ws[i] = w[i];
    if (tid < 10) bsh[tid] = bias[tid];
    __syncthreads();

    int warp = tid / 32, lane = tid % 32;
    int row = blockIdx.x*4 + warp;
    float acc[10];
    #pragma unroll
    for (int j = 0; j < 10; j++) acc[j] = 0.0f;

    for (int k = lane; k < 500; k += 32){
        float xv = S4 * (float)g_xq[row*500 + k];   // dequant on the fly (bit-identical)
        #pragma unroll
        for (int j = 0; j < 10; j++) acc[j] += xv * ws[j*500 + k];
    }
    #pragma unroll
    for (int j = 0; j < 10; j++){
        #pragma unroll
        for (int off = 16; off; off >>= 1)
            acc[j] += __shfl_down_sync(0xffffffffu, acc[j], off);
    }
    if (lane == 0){
        float l[10], m = -1e30f;
        #pragma unroll
        for (int j = 0; j < 10; j++){ l[j] = acc[j] + bsh[j]; m = fmaxf(m, l[j]); }
        float s = 0.0f;
        #pragma unroll
        for (int j = 0; j < 10; j++) s += expf(l[j] - m);
        float ls = logf(s);
        #pragma unroll
        for (int j = 0; j < 10; j++) out[row*10 + j] = l[j] - m - ls;
    }
}

// ---------------- launch ----------------
extern "C" void kernel_launch(void* const* d_in, const int* in_sizes, int n_in,
                              void* d_out, int out_size){
    const float* x   = (const float*)d_in[0];
    const float* c1w = (const float*)d_in[1];
    const float* c1b = (const float*)d_in[2];
    const float* c2w = (const float*)d_in[3];
    const float* c2b = (const float*)d_in[4];
    const float* f1w = (const float*)d_in[5];
    const float* f1b = (const float*)d_in[6];
    const float* f2w = (const float*)d_in[7];
    const float* f2b = (const float*)d_in[8];

    minmax_kernel<<<72, 256>>>(c1w, c1b, c2w, c2b, f1w, f1b);
    effs_kernel<<<429, 256>>>(c1w, c1b, c2w, c2b, f1w, f1b);
    conv1_kernel<<<BATCH/2, 384>>>(x);
    conv2_kernel<<<BATCH/2, 256>>>();
    fc1_kernel<<<dim3(BATCH/64, 8), 256>>>();
    fc2_kernel<<<BATCH/4, 128>>>(f2w, f2b, (float*)d_out);
}

// round 15
// speedup vs baseline: 1.0611x; 1.0611x over previous
#include <cuda_runtime.h>
#include <cstdint>

// ---------------- constants (STATS are fixed) ----------------
#define S1 (3.5f/255.0f)   // conv1 stat (-0.5, 3.0)
#define ZP1 36.0f          // trunc(0.5/S1)
#define INV_S2 42.5f       // 255/6  (exact)
#define INV_S3 31.875f     // 255/8  (exact)
#define INV_S4 25.5f       // 255/10 (exact)
#define S4 (10.0f/255.0f)
#define S2C (6.0f/255.0f)
#define S3C (8.0f/255.0f)

#define BATCH 4096
#define C2_CPAD 52

// ---------------- device scratch ----------------
// statically armed for the first (correctness) call; fc2 re-arms for the next call
__device__ unsigned g_mmkey[12] = {0xFFFFFFFFu,0u, 0xFFFFFFFFu,0u, 0xFFFFFFFFu,0u,
                                   0xFFFFFFFFu,0u, 0xFFFFFFFFu,0u, 0xFFFFFFFFu,0u};
__device__ __align__(16) unsigned g_w1lo[5*20];
__device__ __align__(16) unsigned g_w1hi[5*20];
__device__ float g_c1c[20];                              // conv1 const, pre-scaled by INV_S2
__device__ __align__(16) unsigned g_w2q[5*25*C2_CPAD];  // conv2 wq packed: [p][r=ky*5+kx][c]
__device__ float g_b2eff[C2_CPAD];
__device__ __align__(16) unsigned g_fc1q[200*512];      // fc1 wq packed: [kp=200][n pad 512]
__device__ float g_b3eff[512];
__device__ __align__(16) unsigned char g_act1[BATCH*12*5*12*4];
__device__ __align__(16) unsigned char g_act2[BATCH*50*4*4];
__device__ int g_rowsum[BATCH];
__device__ __align__(16) unsigned char g_xq[BATCH*500];  // fc1 output q-values (u8)

// ---------------- helpers ----------------
__device__ __forceinline__ float clip255(float v){ return fminf(fmaxf(v, 0.0f), 255.0f); }
__device__ __forceinline__ unsigned f2key(float f){
    unsigned u = __float_as_uint(f);
    return (u & 0x80000000u) ? ~u : (u | 0x80000000u);
}
__device__ __forceinline__ float key2f(unsigned k){
    return __uint_as_float((k & 0x80000000u) ? (k & 0x7fffffffu) : ~k);
}
__device__ __forceinline__ void get_sz(int t, float& scale, float& zp){
    float mn = key2f(g_mmkey[2*t]);
    float mx = key2f(g_mmkey[2*t+1]);
    scale = (mx - mn) / 255.0f;
    zp = truncf(clip255(-mn / scale));
}
__device__ __forceinline__ void get_szi(int t, float& inv, float& zp){
    float mn = key2f(g_mmkey[2*t]);
    float mx = key2f(g_mmkey[2*t+1]);
    float scale = (mx - mn) / 255.0f;
    inv = 255.0f / (mx - mn);
    zp = truncf(clip255(-mn / scale));
}
__device__ __forceinline__ float qroundi(float v, float inv, float zp){
    return rintf(clip255(zp + v * inv));
}

// ---------------- min/max over 6 param tensors ----------------
__global__ void minmax_kernel(const float* __restrict__ c1w, const float* __restrict__ c1b,
                              const float* __restrict__ c2w, const float* __restrict__ c2b,
                              const float* __restrict__ f1w, const float* __restrict__ f1b){
    __shared__ unsigned smn[256], smx[256];
    int b = blockIdx.x, tid = threadIdx.x;
    const float* p; int n, t, sub, nb;
    if (b < 64)      { t = 4; p = f1w; n = 400000; sub = b;      nb = 64; }
    else if (b < 68) { t = 2; p = c2w; n = 25000;  sub = b - 64; nb = 4;  }
    else if (b == 68){ t = 0; p = c1w; n = 500;    sub = 0;      nb = 1;  }
    else if (b == 69){ t = 1; p = c1b; n = 20;     sub = 0;      nb = 1;  }
    else if (b == 70){ t = 3; p = c2b; n = 50;     sub = 0;      nb = 1;  }
    else             { t = 5; p = f1b; n = 500;    sub = 0;      nb = 1;  }

    unsigned lmin = 0xFFFFFFFFu, lmax = 0u;
    for (int i = sub*256 + tid; i < n; i += nb*256){
        unsigned k = f2key(p[i]);
        lmin = min(lmin, k); lmax = max(lmax, k);
    }
    smn[tid] = lmin; smx[tid] = lmax;
    __syncthreads();
    for (int s = 128; s; s >>= 1){
        if (tid < s){
            smn[tid] = min(smn[tid], smn[tid+s]);
            smx[tid] = max(smx[tid], smx[tid+s]);
        }
        __syncthreads();
    }
    if (tid == 0){
        atomicMin(&g_mmkey[2*t],   smn[0]);
        atomicMax(&g_mmkey[2*t+1], smx[0]);
    }
}

// ---------------- build packed weights / constants ----------------
__global__ void effs_kernel(const float* __restrict__ c1w, const float* __restrict__ c1b,
                            const float* __restrict__ c2w, const float* __restrict__ c2b,
                            const float* __restrict__ f1w, const float* __restrict__ f1b){
    int idx = blockIdx.x*blockDim.x + threadIdx.x;
    if (idx < 100){
        int ky = idx / 20, ch = idx % 20;
        float iv, z; get_szi(0, iv, z);
        unsigned lo = 0u;
        #pragma unroll
        for (int j = 0; j < 4; j++){
            unsigned wq = (unsigned)qroundi(c1w[ch*25 + ky*5 + j], iv, z);
            lo |= (wq & 0xffu) << (8*j);
        }
        g_w1lo[idx] = lo;
        g_w1hi[idx] = (unsigned)qroundi(c1w[ch*25 + ky*5 + 4], iv, z) & 0xffu;
    } else if (idx < 120){
        int ch = idx - 100;
        float iv, z; get_szi(0, iv, z);
        float s, zz; get_sz(0, s, zz);
        float wsum = 0.0f;
        for (int k = 0; k < 25; k++) wsum += qroundi(c1w[ch*25 + k], iv, z);
        float ivb, zb; get_szi(1, ivb, zb);
        float sb, zb2; get_sz(1, sb, zb2);
        float beff = sb * (qroundi(c1b[ch], ivb, zb) + zb);
        g_c1c[ch] = (beff + (S1 * s) * (900.0f * z - 36.0f * wsum)) * INV_S2;
    } else if (idx < 6620){                               // conv2 wq packed [p][r][c]
        int e = idx - 120;
        int p = e / (25*C2_CPAD), r = (e / C2_CPAD) % 25, c = e % C2_CPAD;
        unsigned pk = 0u;
        if (c < 50){
            float iv, z; get_szi(2, iv, z);
            #pragma unroll
            for (int j = 0; j < 4; j++){
                int ci = p*4 + j;
                unsigned wq = (unsigned)qroundi(c2w[c*500 + ci*25 + r], iv, z);
                pk |= (wq & 0xffu) << (8*j);
            }
        }
        g_w2q[e] = pk;
    } else if (idx < 6672){
        int c = idx - 6620;
        float val = 0.0f;
        if (c < 50){
            float s, z; get_sz(3, s, z);
            val = s * (qroundi(c2b[c], 255.0f/( (key2f(g_mmkey[7]) - key2f(g_mmkey[6])) ), z) + z);
        }
        g_b2eff[c] = val;
    } else if (idx < 109072){
        int e = idx - 6672;
        int kp = e / 512, n = e % 512;
        unsigned pk = 0u;
        if (n < 500){
            float iv, z; get_szi(4, iv, z);
            #pragma unroll
            for (int j = 0; j < 4; j++){
                int k = kp*4 + j;
                unsigned wq = (unsigned)qroundi(f1w[n*800 + k], iv, z);
                pk |= (wq & 0xffu) << (8*j);
            }
        }
        g_fc1q[e] = pk;
    } else if (idx < 109584){
        int n = idx - 109072;
        float val = 0.0f;
        if (n < 500){
            float iv, z; get_szi(5, iv, z);
            float s, zz; get_sz(5, s, zz);
            val = s * (qroundi(f1b[n], iv, z) + z);
        }
        g_b3eff[n] = val;
    }
}

// ---------------- conv1 via dp4a, fused integer pool + quant (2 images/block) ----------------
__global__ void __launch_bounds__(384, 3) conv1_kernel(const float* __restrict__ x){
    __shared__ unsigned q0u[2][28*8];
    __shared__ unsigned Wn[2][28*28];
    __shared__ unsigned Ps[2][24*24];
    __shared__ unsigned wlo_s[100], whi_s[100];
    __shared__ float cc_s[20];

    int imgbase = blockIdx.x * 2, tid = threadIdx.x;

    for (int i = tid; i < 448; i += 384){
        int im = i / 224, e = i % 224;
        int r = e / 8, c4 = e % 8;
        unsigned pk = 0u;
        if (c4 < 7){
            const float* xi = x + (imgbase + im)*784;
            #pragma unroll
            for (int j = 0; j < 4; j++){
                float v = xi[r*28 + c4*4 + j];
                unsigned q = (unsigned)rintf(clip255(ZP1 + v / S1));
                pk |= (q & 0xffu) << (8*j);
            }
        }
        q0u[im][r*8 + c4] = pk;
    }
    for (int i = tid; i < 100; i += 384){ wlo_s[i] = g_w1lo[i]; whi_s[i] = g_w1hi[i]; }
    if (tid < 20) cc_s[tid] = g_c1c[tid];
    __syncthreads();

    for (int i = tid; i < 1568; i += 384){
        int im = i / 784, e = i % 784;
        int r = e / 28, xx = e % 28;
        unsigned a = q0u[im][r*8 + (xx >> 2)];
        unsigned b = q0u[im][r*8 + (xx >> 2) + 1];
        Wn[im][e] = __funnelshift_r(a, b, 8*(xx & 3));
    }
    __syncthreads();

    for (int i = tid; i < 1152; i += 384){
        int im = i / 576, e = i % 576;
        int y = e / 24, xx = e % 24;
        unsigned s = 0;
        #pragma unroll
        for (int ky = 0; ky < 5; ky++){
            s = __dp4a(Wn[im][(y + ky)*28 + xx], 0x01010101u, s);
            s += (q0u[im][(y + ky)*8 + ((xx + 4) >> 2)] >> (8*((xx + 4) & 3))) & 0xffu;
        }
        Ps[im][e] = s;
    }
    __syncthreads();

    if (tid < 360){
        int rr = tid / 30;
        int t  = tid % 30;
        int cg = t / 6, xp = t % 6;
        int x0 = xp * 4;

        float s_w, z_w; get_sz(0, s_w, z_w);
        float Af = S1 * s_w * INV_S2;
        int zpi = (int)z_w;

        #pragma unroll 1
        for (int im = 0; im < 2; im++){
            unsigned acc[2][4][4] = {};

            #pragma unroll
            for (int ir = 0; ir < 6; ir++){
                const uint4* w4 = (const uint4*)&Wn[im][(2*rr + ir)*28 + x0];
                uint4 lo4 = w4[0], hi4 = w4[1];
                unsigned wn[8] = {lo4.x,lo4.y,lo4.z,lo4.w, hi4.x,hi4.y,hi4.z,hi4.w};
                #pragma unroll
                for (int row = 0; row < 2; row++){
                    int ky = ir - row;
                    if (ky >= 0 && ky <= 4){
                        uint4 wlo = *(const uint4*)&wlo_s[ky*20 + cg*4];
                        uint4 whi = *(const uint4*)&whi_s[ky*20 + cg*4];
                        #pragma unroll
                        for (int c = 0; c < 4; c++){
                            unsigned wl = wn[c], wh = wn[c + 4];
                            acc[row][c][0] = __dp4a(wl, wlo.x, acc[row][c][0]);
                            acc[row][c][1] = __dp4a(wl, wlo.y, acc[row][c][1]);
                            acc[row][c][2] = __dp4a(wl, wlo.z, acc[row][c][2]);
                            acc[row][c][3] = __dp4a(wl, wlo.w, acc[row][c][3]);
                            acc[row][c][0] = __dp4a(wh, whi.x, acc[row][c][0]);
                            acc[row][c][1] = __dp4a(wh, whi.y, acc[row][c][1]);
                            acc[row][c][2] = __dp4a(wh, whi.z, acc[row][c][2]);
                            acc[row][c][3] = __dp4a(wh, whi.w, acc[row][c][3]);
                        }
                    }
                }
            }

            int ZP[2][4];
            #pragma unroll
            for (int rw = 0; rw < 2; rw++)
                #pragma unroll
                for (int cl = 0; cl < 4; cl++)
                    ZP[rw][cl] = zpi * (int)Ps[im][(2*rr + rw)*24 + x0 + cl];

            unsigned ow0 = 0u, ow1 = 0u;
            #pragma unroll
            for (int c = 0; c < 4; c++){
                float Cc = cc_s[cg*4 + c];
                #pragma unroll
                for (int px = 0; px < 2; px++){
                    int i0 = (int)acc[0][2*px    ][c] - ZP[0][2*px    ];
                    int i1 = (int)acc[0][2*px + 1][c] - ZP[0][2*px + 1];
                    int i2 = (int)acc[1][2*px    ][c] - ZP[1][2*px    ];
                    int i3 = (int)acc[1][2*px + 1][c] - ZP[1][2*px + 1];
                    int imx = max(max(i0, i1), max(i2, i3));
                    float q = rintf(fmaxf(Af*(float)imx + Cc, 0.0f));
                    unsigned qb = ((unsigned)q & 0xffu) << (8*c);
                    if (px == 0) ow0 |= qb; else ow1 |= qb;
                }
            }
            unsigned* dst = (unsigned*)g_act1 + (((imgbase + im)*12 + rr)*5 + cg)*12 + xp*2;
            dst[0] = ow0; dst[1] = ow1;
        }
    }
}

// ---------------- conv2: heterogeneous blocks — even bid = int8 mma, odd bid = dp4a ----------------
// dp4a branch retiled to 4x4 accumulators (round-14 fix: fits under the 5-block reg cap, no spills).
#define CV2_XS   0                          // 5760 B  (2*720 u32)
#define CV2_SW   5760                       // 512 B   (2*64 u32)
#define CV2_BEFF 6272                       // 208 B
#define CV2_RSUM 6480                       // 16 B
#define CV2_Q2   6496                       // 6656 B  (2*52*64)
#define CV2_WB   13152                      // branch area
#define CV2_TOTAL (CV2_WB + 28672 + 512)    // mma: Bs 28672 + offA 512 -> 42336 B

__global__ void __launch_bounds__(256, 5) conv2_kernel(){
    __shared__ __align__(16) char smu[CV2_TOTAL];
    unsigned* Xs      = (unsigned*)(smu + CV2_XS);    // [li][y][p][x]
    unsigned* Sw      = (unsigned*)(smu + CV2_SW);    // [li][64]
    float*    beff_s  = (float*)(smu + CV2_BEFF);
    int*      rsum    = (int*)(smu + CV2_RSUM);
    unsigned char* q2 = (unsigned char*)(smu + CV2_Q2); // [li][ch pad52][8][8]
    unsigned* Bs      = (unsigned*)(smu + CV2_WB);    // mma: [g = r*5+p][56]
    int*      offA    = (int*)(smu + CV2_WB + 28672);
    unsigned* Wq_s    = (unsigned*)(smu + CV2_WB);    // dp4a: [p*25 + r][52]

    int tid = threadIdx.x;
    int bid = blockIdx.x;
    int imgbase = bid * 2;
    bool is_mma = (bid & 1) == 0;     // block-uniform

    // common: load act1 tiles
    {
        const uint4* xsrc = (const uint4*)(g_act1 + imgbase*2880);
        for (int i = tid; i < 360; i += 256) ((uint4*)Xs)[i] = xsrc[i];
    }
    if (is_mma){
        for (int i = tid; i < 128*14; i += 256){
            int g = i / 14, c4 = i % 14;
            uint4 v = make_uint4(0u,0u,0u,0u);
            if (g < 125 && c4 < 13){
                int r = g / 5, p = g % 5;
                v = *(const uint4*)&g_w2q[(p*25 + r)*C2_CPAD + c4*4];
            }
            ((uint4*)Bs)[g*14 + c4] = v;
        }
        if (tid < 128){
            int g = tid;
            int r = (g < 125) ? g/5 : 0, p = (g < 125) ? g%5 : 0;
            offA[tid] = (r/5)*60 + p*12 + (r%5);
        }
    } else {
        for (int i = tid; i < 1625; i += 256)
            ((uint4*)Wq_s)[i] = ((const uint4*)g_w2q)[i];
    }
    if (tid < C2_CPAD) beff_s[tid] = g_b2eff[tid];
    if (tid < 2) rsum[tid] = 0;
    __syncthreads();

    // common: window sums (for zp correction)
    if (tid < 128){
        int li = tid >> 6, pos = tid & 63;
        int oy = pos >> 3, ox = pos & 7;
        unsigned s = 0;
        for (int ky = 0; ky < 5; ky++)
            for (int p = 0; p < 5; p++){
                const unsigned* row = &Xs[li*720 + (oy + ky)*60 + p*12];
                #pragma unroll
                for (int kx = 0; kx < 5; kx++)
                    s = __dp4a(row[ox + kx], 0x01010101u, s);
            }
        Sw[tid] = s;
    }
    __syncthreads();   // Sw ready for both branches' epilogues

    float s2w, z2w; get_sz(2, s2w, z2w);
    float S2s = S2C * s2w;
    int zp2 = (int)z2w;

    if (is_mma){
        // ---- tensor path (round-8 proven) ----
        int w = tid >> 5, l = tid & 31;
        int li = w >> 2, mtile = w & 3;
        int lr = l >> 2, lc = l & 3;
        int oy0 = mtile*2;
        int base0 = li*720 + oy0*60 + lr;
        int base1 = base0 + 60;

        int acc[7][4];
        #pragma unroll
        for (int t = 0; t < 7; t++)
            #pragma unroll
            for (int j = 0; j < 4; j++) acc[t][j] = 0;

        #pragma unroll 1
        for (int step = 0; step < 16; step++){
            int g0 = step*8 + lc;
            int g1 = g0 + 4;
            unsigned a0 = Xs[base0 + offA[g0]];
            unsigned a1 = Xs[base1 + offA[g0]];
            unsigned a2 = Xs[base0 + offA[g1]];
            unsigned a3 = Xs[base1 + offA[g1]];
            const unsigned* b0r = &Bs[g0*56 + lr];
            const unsigned* b1r = &Bs[g1*56 + lr];
            #pragma unroll
            for (int t = 0; t < 7; t++){
                unsigned b0 = b0r[t*8];
                unsigned b1 = b1r[t*8];
                asm volatile(
                    "mma.sync.aligned.m16n8k32.row.col.s32.u8.u8.s32 "
                    "{%0,%1,%2,%3}, {%4,%5,%6,%7}, {%8,%9}, {%0,%1,%2,%3};"
                    : "+r"(acc[t][0]), "+r"(acc[t][1]), "+r"(acc[t][2]), "+r"(acc[t][3])
                    : "r"(a0), "r"(a1), "r"(a2), "r"(a3), "r"(b0), "r"(b1));
            }
        }

        #pragma unroll
        for (int half = 0; half < 2; half++){
            int oy = oy0 + half, ox = lr;
            int sw = (int)Sw[li*64 + oy*8 + ox];
            #pragma unroll
            for (int t = 0; t < 7; t++){
                #pragma unroll
                for (int j = 0; j < 2; j++){
                    int ch = t*8 + lc*2 + j;
                    if (ch < C2_CPAD){
                        int cval = acc[t][half*2 + j];
                        float val = S2s * (float)(cval - zp2*sw) + beff_s[ch];
                        float v = rintf(fmaxf(val * INV_S3, 0.0f));
                        q2[((li*C2_CPAD + ch)*8 + oy)*8 + ox] = (unsigned char)(unsigned)v;
                    }
                }
            }
        }
    } else {
        // ---- dp4a path, 4x4 tiles: task = (li, y, xh, cg), 416 tasks over 256 threads ----
        #pragma unroll 1
        for (int t = tid; t < 416; t += 256){
            int li = t / 208, rest = t % 208;
            int y = rest / 26, sub = rest % 26;
            int xh = sub / 13, cg = sub % 13;
            int xb = xh * 4;

            unsigned acc[4][4];
            #pragma unroll
            for (int xx = 0; xx < 4; xx++)
                #pragma unroll
                for (int c = 0; c < 4; c++) acc[xx][c] = 0u;

            #pragma unroll 1
            for (int p = 0; p < 5; p++){
                #pragma unroll
                for (int ky = 0; ky < 5; ky++){
                    const unsigned* xr = &Xs[li*720 + (y + ky)*60 + p*12 + xb];
                    uint4 a0 = *(const uint4*)xr;
                    uint4 a1 = *(const uint4*)(xr + 4);
                    unsigned xv[8] = {a0.x,a0.y,a0.z,a0.w, a1.x,a1.y,a1.z,a1.w};
                    #pragma unroll
                    for (int kx = 0; kx < 5; kx++){
                        uint4 wq = *(const uint4*)&Wq_s[(p*25 + ky*5 + kx)*C2_CPAD + cg*4];
                        #pragma unroll
                        for (int xx = 0; xx < 4; xx++){
                            unsigned xvv = xv[xx + kx];
                            acc[xx][0] = __dp4a(xvv, wq.x, acc[xx][0]);
                            acc[xx][1] = __dp4a(xvv, wq.y, acc[xx][1]);
                            acc[xx][2] = __dp4a(xvv, wq.z, acc[xx][2]);
                            acc[xx][3] = __dp4a(xvv, wq.w, acc[xx][3]);
                        }
                    }
                }
            }

            #pragma unroll
            for (int c = 0; c < 4; c++){
                int ch = cg*4 + c;
                float beff = beff_s[ch];
                #pragma unroll
                for (int xx = 0; xx < 4; xx++){
                    int sw = (int)Sw[li*64 + y*8 + xb + xx];
                    int idiff = (int)acc[xx][c] - zp2*sw;
                    float val = S2s * (float)idiff + beff;
                    float v = rintf(fmaxf(val * INV_S3, 0.0f));
                    q2[((li*C2_CPAD + ch)*8 + y)*8 + xb + xx] = (unsigned char)(unsigned)v;
                }
            }
        }
    }
    __syncthreads();

    // common: pool 2x2 + per-image rowsum
    int lsum0 = 0, lsum1 = 0;
    for (int i = tid; i < 1600; i += 256){
        int im = i / 800, rest = i % 800;
        int ch = rest / 16, pr = (rest % 16) / 4, pc = rest % 4;
        const unsigned char* bp = q2 + ((im*C2_CPAD + ch)*8 + 2*pr)*8 + 2*pc;
        unsigned char m = max(max(bp[0], bp[1]), max(bp[8], bp[9]));
        g_act2[((imgbase + im)*50 + ch)*16 + pr*4 + pc] = m;
        if (im == 0) lsum0 += m; else lsum1 += m;
    }
    #pragma unroll
    for (int off = 16; off; off >>= 1){
        lsum0 += __shfl_down_sync(0xffffffffu, lsum0, off);
        lsum1 += __shfl_down_sync(0xffffffffu, lsum1, off);
    }
    if ((tid & 31) == 0){
        if (lsum0) atomicAdd(&rsum[0], lsum0);
        if (lsum1) atomicAdd(&rsum[1], lsum1);
    }
    __syncthreads();
    if (tid < 2) g_rowsum[imgbase + tid] = rsum[tid];
}

// ---------------- fc1 via int8 mma + quant; output u8 q-values ----------------
__global__ void __launch_bounds__(256) fc1_kernel(){
    __shared__ unsigned As[64*44];
    __shared__ unsigned Bs[40*72];

    int tid = threadIdx.x;
    int w = tid >> 5, l = tid & 31;
    int lr = l >> 2, lc = l & 3;
    int m0 = blockIdx.x * 64, n0 = blockIdx.y * 64;
    int wm = (w & 1) * 32;
    int wn = (w >> 1) * 16;

    int acc[2][2][4];
    #pragma unroll
    for (int mt = 0; mt < 2; mt++)
        #pragma unroll
        for (int nt = 0; nt < 2; nt++)
            #pragma unroll
            for (int j = 0; j < 4; j++) acc[mt][nt][j] = 0;

    const unsigned* Xg = (const unsigned*)g_act2;

    #pragma unroll 1
    for (int chunk = 0; chunk < 5; chunk++){
        for (int i = tid; i < 640; i += 256){
            int r = i / 10, c4 = i % 10;
            uint4 v = *(const uint4*)&Xg[(m0 + r)*200 + chunk*40 + c4*4];
            *(uint4*)&As[r*44 + c4*4] = v;
        }
        for (int i = tid; i < 640; i += 256){
            int kr = i / 16, c4 = i % 16;
            uint4 v = *(const uint4*)&g_fc1q[(chunk*40 + kr)*512 + n0 + c4*4];
            *(uint4*)&Bs[kr*72 + c4*4] = v;
        }
        __syncthreads();

        #pragma unroll
        for (int s = 0; s < 5; s++){
            int g = s*8;
            unsigned a[2][4];
            #pragma unroll
            for (int mt = 0; mt < 2; mt++){
                int r0 = wm + mt*16 + lr;
                a[mt][0] = As[r0*44 + g + lc];
                a[mt][1] = As[(r0 + 8)*44 + g + lc];
                a[mt][2] = As[r0*44 + g + 4 + lc];
                a[mt][3] = As[(r0 + 8)*44 + g + 4 + lc];
            }
            unsigned b[2][2];
            #pragma unroll
            for (int nt = 0; nt < 2; nt++){
                int nn = wn + nt*8 + lr;
                b[nt][0] = Bs[(g + lc)*72 + nn];
                b[nt][1] = Bs[(g + 4 + lc)*72 + nn];
            }
            #pragma unroll
            for (int mt = 0; mt < 2; mt++)
                #pragma unroll
                for (int nt = 0; nt < 2; nt++){
                    asm volatile(
                        "mma.sync.aligned.m16n8k32.row.col.s32.u8.u8.s32 "
                        "{%0,%1,%2,%3}, {%4,%5,%6,%7}, {%8,%9}, {%0,%1,%2,%3};"
                        : "+r"(acc[mt][nt][0]), "+r"(acc[mt][nt][1]),
                          "+r"(acc[mt][nt][2]), "+r"(acc[mt][nt][3])
                        : "r"(a[mt][0]), "r"(a[mt][1]), "r"(a[mt][2]), "r"(a[mt][3]),
                          "r"(b[nt][0]), "r"(b[nt][1]));
                }
        }
        __syncthreads();
    }

    float s3w, z3w; get_sz(4, s3w, z3w);
    float S3s = S3C * s3w;
    int zp3 = (int)z3w;

    #pragma unroll
    for (int mt = 0; mt < 2; mt++){
        int mr0 = m0 + wm + mt*16 + lr;
        int rs0 = g_rowsum[mr0];
        int rs1 = g_rowsum[mr0 + 8];
        #pragma unroll
        for (int nt = 0; nt < 2; nt++){
            int nb = n0 + wn + nt*8 + 2*lc;
            #pragma unroll
            for (int j = 0; j < 2; j++){
                int n = nb + j;
                if (n < 500){
                    float y0 = S3s * (float)(acc[mt][nt][j]     - zp3 * rs0) + g_b3eff[n];
                    float v0 = rintf(fmaxf(y0 * INV_S4, 0.0f));
                    g_xq[mr0*500 + n] = (unsigned char)((unsigned)v0 & 0xffu);
                    float y1 = S3s * (float)(acc[mt][nt][2 + j] - zp3 * rs1) + g_b3eff[n];
                    float v1 = rintf(fmaxf(y1 * INV_S4, 0.0f));
                    g_xq[(mr0 + 8)*500 + n] = (unsigned char)((unsigned)v1 & 0xffu);
                }
            }
        }
    }
}

// ---------------- fc2 + log_softmax (+ re-arm minmax keys for next run) ----------------
__global__ void __launch_bounds__(128) fc2_kernel(const float* __restrict__ w,
                                                  const float* __restrict__ bias,
                                                  float* __restrict__ out){
    __shared__ float ws[5000];
    __shared__ float bsh[10];
    int tid = threadIdx.x;

    if (blockIdx.x == 0 && tid < 12)
        g_mmkey[tid] = (tid & 1) ? 0u : 0xFFFFFFFFu;

    for (int i = tid; i < 5000; i += 128) ws[i] = w[i];
    if (tid < 10) bsh[tid] = bias[tid];
    __syncthreads();

    int warp = tid / 32, lane = tid % 32;
    int row = blockIdx.x*4 + warp;
    float acc[10];
    #pragma unroll
    for (int j = 0; j < 10; j++) acc[j] = 0.0f;

    for (int k = lane; k < 500; k += 32){
        float xv = S4 * (float)g_xq[row*500 + k];   // dequant on the fly (bit-identical)
        #pragma unroll
        for (int j = 0; j < 10; j++) acc[j] += xv * ws[j*500 + k];
    }
    #pragma unroll
    for (int j = 0; j < 10; j++){
        #pragma unroll
        for (int off = 16; off; off >>= 1)
            acc[j] += __shfl_down_sync(0xffffffffu, acc[j], off);
    }
    if (lane == 0){
        float l[10], m = -1e30f;
        #pragma unroll
        for (int j = 0; j < 10; j++){ l[j] = acc[j] + bsh[j]; m = fmaxf(m, l[j]); }
        float s = 0.0f;
        #pragma unroll
        for (int j = 0; j < 10; j++) s += expf(l[j] - m);
        float ls = logf(s);
        #pragma unroll
        for (int j = 0; j < 10; j++) out[row*10 + j] = l[j] - m - ls;
    }
}

// ---------------- launch ----------------
extern "C" void kernel_launch(void* const* d_in, const int* in_sizes, int n_in,
                              void* d_out, int out_size){
    const float* x   = (const float*)d_in[0];
    const float* c1w = (const float*)d_in[1];
    const float* c1b = (const float*)d_in[2];
    const float* c2w = (const float*)d_in[3];
    const float* c2b = (const float*)d_in[4];
    const float* f1w = (const float*)d_in[5];
    const float* f1b = (const float*)d_in[6];
    const float* f2w = (const float*)d_in[7];
    const float* f2b = (const float*)d_in[8];

    minmax_kernel<<<72, 256>>>(c1w, c1b, c2w, c2b, f1w, f1b);
    effs_kernel<<<429, 256>>>(c1w, c1b, c2w, c2b, f1w, f1b);
    conv1_kernel<<<BATCH/2, 384>>>(x);
    conv2_kernel<<<BATCH/2, 256>>>();
    fc1_kernel<<<dim3(BATCH/64, 8), 256>>>();
    fc2_kernel<<<BATCH/4, 128>>>(f2w, f2b, (float*)d_out);
}

// round 17
// speedup vs baseline: 1.2159x; 1.1458x over previous
#include <cuda_runtime.h>
#include <cstdint>

// ---------------- constants (STATS are fixed) ----------------
#define S1 (3.5f/255.0f)
#define ZP1 36.0f
#define INV_S2 42.5f
#define INV_S3 31.875f
#define INV_S4 25.5f
#define S4 (10.0f/255.0f)
#define S2C (6.0f/255.0f)
#define S3C (8.0f/255.0f)

#define BATCH 4096
#define C2_CPAD 52

// ---------------- device scratch ----------------
__device__ unsigned g_mmkey[12] = {0xFFFFFFFFu,0u, 0xFFFFFFFFu,0u, 0xFFFFFFFFu,0u,
                                   0xFFFFFFFFu,0u, 0xFFFFFFFFu,0u, 0xFFFFFFFFu,0u};
__device__ __align__(16) unsigned g_w1lo[5*20];
__device__ __align__(16) unsigned g_w1hi[5*20];
__device__ float g_c1c[20];
__device__ __align__(16) unsigned g_w2q[5*25*C2_CPAD];  // conv2 wq packed: [p][r=ky*5+kx][c]
__device__ float g_b2eff[C2_CPAD];
__device__ __align__(16) unsigned g_fc1q[200*512];
__device__ float g_b3eff[512];
__device__ __align__(16) unsigned char g_act2[BATCH*50*4*4];
__device__ int g_rowsum[BATCH];
__device__ __align__(16) unsigned char g_xq[BATCH*500];

// ---------------- helpers ----------------
__device__ __forceinline__ float clip255(float v){ return fminf(fmaxf(v, 0.0f), 255.0f); }
__device__ __forceinline__ unsigned f2key(float f){
    unsigned u = __float_as_uint(f);
    return (u & 0x80000000u) ? ~u : (u | 0x80000000u);
}
__device__ __forceinline__ float key2f(unsigned k){
    return __uint_as_float((k & 0x80000000u) ? (k & 0x7fffffffu) : ~k);
}
__device__ __forceinline__ void get_sz(int t, float& scale, float& zp){
    float mn = key2f(g_mmkey[2*t]);
    float mx = key2f(g_mmkey[2*t+1]);
    scale = (mx - mn) / 255.0f;
    zp = truncf(clip255(-mn / scale));
}
__device__ __forceinline__ void get_szi(int t, float& inv, float& zp){
    float mn = key2f(g_mmkey[2*t]);
    float mx = key2f(g_mmkey[2*t+1]);
    float scale = (mx - mn) / 255.0f;
    inv = 255.0f / (mx - mn);
    zp = truncf(clip255(-mn / scale));
}
__device__ __forceinline__ float qroundi(float v, float inv, float zp){
    return rintf(clip255(zp + v * inv));
}

// ---------------- min/max over 6 param tensors ----------------
__global__ void minmax_kernel(const float* __restrict__ c1w, const float* __restrict__ c1b,
                              const float* __restrict__ c2w, const float* __restrict__ c2b,
                              const float* __restrict__ f1w, const float* __restrict__ f1b){
    __shared__ unsigned smn[256], smx[256];
    int b = blockIdx.x, tid = threadIdx.x;
    const float* p; int n, t, sub, nb;
    if (b < 64)      { t = 4; p = f1w; n = 400000; sub = b;      nb = 64; }
    else if (b < 68) { t = 2; p = c2w; n = 25000;  sub = b - 64; nb = 4;  }
    else if (b == 68){ t = 0; p = c1w; n = 500;    sub = 0;      nb = 1;  }
    else if (b == 69){ t = 1; p = c1b; n = 20;     sub = 0;      nb = 1;  }
    else if (b == 70){ t = 3; p = c2b; n = 50;     sub = 0;      nb = 1;  }
    else             { t = 5; p = f1b; n = 500;    sub = 0;      nb = 1;  }

    unsigned lmin = 0xFFFFFFFFu, lmax = 0u;
    for (int i = sub*256 + tid; i < n; i += nb*256){
        unsigned k = f2key(p[i]);
        lmin = min(lmin, k); lmax = max(lmax, k);
    }
    smn[tid] = lmin; smx[tid] = lmax;
    __syncthreads();
    for (int s = 128; s; s >>= 1){
        if (tid < s){
            smn[tid] = min(smn[tid], smn[tid+s]);
            smx[tid] = max(smx[tid], smx[tid+s]);
        }
        __syncthreads();
    }
    if (tid == 0){
        atomicMin(&g_mmkey[2*t],   smn[0]);
        atomicMax(&g_mmkey[2*t+1], smx[0]);
    }
}

// ---------------- build packed weights / constants ----------------
__global__ void effs_kernel(const float* __restrict__ c1w, const float* __restrict__ c1b,
                            const float* __restrict__ c2w, const float* __restrict__ c2b,
                            const float* __restrict__ f1w, const float* __restrict__ f1b){
    int idx = blockIdx.x*blockDim.x + threadIdx.x;
    if (idx < 100){
        int ky = idx / 20, ch = idx % 20;
        float iv, z; get_szi(0, iv, z);
        unsigned lo = 0u;
        #pragma unroll
        for (int j = 0; j < 4; j++){
            unsigned wq = (unsigned)qroundi(c1w[ch*25 + ky*5 + j], iv, z);
            lo |= (wq & 0xffu) << (8*j);
        }
        g_w1lo[idx] = lo;
        g_w1hi[idx] = (unsigned)qroundi(c1w[ch*25 + ky*5 + 4], iv, z) & 0xffu;
    } else if (idx < 120){
        int ch = idx - 100;
        float iv, z; get_szi(0, iv, z);
        float s, zz; get_sz(0, s, zz);
        float wsum = 0.0f;
        for (int k = 0; k < 25; k++) wsum += qroundi(c1w[ch*25 + k], iv, z);
        float ivb, zb; get_szi(1, ivb, zb);
        float sb, zb2; get_sz(1, sb, zb2);
        float beff = sb * (qroundi(c1b[ch], ivb, zb) + zb);
        g_c1c[ch] = (beff + (S1 * s) * (900.0f * z - 36.0f * wsum)) * INV_S2;
    } else if (idx < 6620){                               // conv2 wq packed [p][r][c]
        int e = idx - 120;
        int p = e / (25*C2_CPAD), r = (e / C2_CPAD) % 25, c = e % C2_CPAD;
        unsigned pk = 0u;
        if (c < 50){
            float iv, z; get_szi(2, iv, z);
            #pragma unroll
            for (int j = 0; j < 4; j++){
                int ci = p*4 + j;
                unsigned wq = (unsigned)qroundi(c2w[c*500 + ci*25 + r], iv, z);
                pk |= (wq & 0xffu) << (8*j);
            }
        }
        g_w2q[e] = pk;
    } else if (idx < 6672){
        int c = idx - 6620;
        float val = 0.0f;
        if (c < 50){
            float s, z; get_sz(3, s, z);
            float iv3 = 255.0f / (key2f(g_mmkey[7]) - key2f(g_mmkey[6]));
            val = s * (qroundi(c2b[c], iv3, z) + z);
        }
        g_b2eff[c] = val;
    } else if (idx < 109072){
        int e = idx - 6672;
        int kp = e / 512, n = e % 512;
        unsigned pk = 0u;
        if (n < 500){
            float iv, z; get_szi(4, iv, z);
            #pragma unroll
            for (int j = 0; j < 4; j++){
                int k = kp*4 + j;
                unsigned wq = (unsigned)qroundi(f1w[n*800 + k], iv, z);
                pk |= (wq & 0xffu) << (8*j);
            }
        }
        g_fc1q[e] = pk;
    } else if (idx < 109584){
        int n = idx - 109072;
        float val = 0.0f;
        if (n < 500){
            float iv, z; get_szi(5, iv, z);
            float s, zz; get_sz(5, s, zz);
            val = s * (qroundi(f1b[n], iv, z) + z);
        }
        g_b3eff[n] = val;
    }
}

// ---------------- fused conv1 (dp4a) + conv2 (int8 mma) per block, 2 images ----------------
// conv1 output stays in smem (Xs), consumed directly by conv2. Phase skew across
// resident blocks overlaps the dp4a/alu phase with the tensor phase.
__global__ void __launch_bounds__(256) convfused_kernel(const float* __restrict__ x){
    __shared__ __align__(16) unsigned Xs[2*720];          // conv1 out / conv2 in: [li][y][p][xx]
    __shared__ unsigned Sw[128];
    __shared__ float beff_s[C2_CPAD];
    __shared__ int rsum[2];
    __shared__ unsigned char q2[2*C2_CPAD*64];
    __shared__ __align__(16) char WB[29184];              // union scratch

    // conv1 views
    unsigned* q0u   = (unsigned*)(WB);                    // 448 u32   [im*224 + r*8 + c4]
    unsigned* Wn    = (unsigned*)(WB + 1792);             // 1568 u32  [im*784 + r*28 + xx]
    unsigned* Ps    = (unsigned*)(WB + 8064);             // 1152 u32  [im*576 + y*24 + xx]
    unsigned* wlo_s = (unsigned*)(WB + 12672);            // 100
    unsigned* whi_s = (unsigned*)(WB + 13072);            // 100
    float*    cc_s  = (float*)(WB + 13472);               // 20
    // conv2 views (valid after conv1 phase)
    unsigned* Bs    = (unsigned*)(WB);                    // [g = r*5+p][56]
    int*      offA  = (int*)(WB + 28672);                 // 128

    int tid = threadIdx.x;
    int imgbase = blockIdx.x * 2;

    // ===== conv1 phase =====
    for (int i = tid; i < 448; i += 256){
        int im = i / 224, e = i % 224;
        int r = e / 8, c4 = e % 8;
        unsigned pk = 0u;
        if (c4 < 7){
            const float* xi = x + (imgbase + im)*784;
            #pragma unroll
            for (int j = 0; j < 4; j++){
                float v = xi[r*28 + c4*4 + j];
                unsigned q = (unsigned)rintf(clip255(ZP1 + v / S1));
                pk |= (q & 0xffu) << (8*j);
            }
        }
        q0u[i] = pk;
    }
    for (int i = tid; i < 100; i += 256){ wlo_s[i] = g_w1lo[i]; whi_s[i] = g_w1hi[i]; }
    if (tid < 20) cc_s[tid] = g_c1c[tid];
    __syncthreads();

    for (int i = tid; i < 1568; i += 256){
        int im = i / 784, e = i % 784;
        int r = e / 28, xx = e % 28;
        unsigned a = q0u[im*224 + r*8 + (xx >> 2)];
        unsigned b = q0u[im*224 + r*8 + (xx >> 2) + 1];
        Wn[i] = __funnelshift_r(a, b, 8*(xx & 3));
    }
    __syncthreads();

    for (int i = tid; i < 1152; i += 256){
        int im = i / 576, e = i % 576;
        int y = e / 24, xx = e % 24;
        unsigned s = 0;
        #pragma unroll
        for (int ky = 0; ky < 5; ky++){
            s = __dp4a(Wn[im*784 + (y + ky)*28 + xx], 0x01010101u, s);
            s += (q0u[im*224 + (y + ky)*8 + ((xx + 4) >> 2)] >> (8*((xx + 4) & 3))) & 0xffu;
        }
        Ps[i] = s;
    }
    __syncthreads();

    {
        float s_w, z_w; get_sz(0, s_w, z_w);
        float Af = S1 * s_w * INV_S2;
        int zpi = (int)z_w;

        #pragma unroll 1
        for (int t = tid; t < 720; t += 256){
            int im = t / 360, tt = t % 360;
            int rr = tt / 30, t2 = tt % 30;
            int cg = t2 / 6, xp = t2 % 6;
            int x0 = xp * 4;

            unsigned acc[2][4][4] = {};
            #pragma unroll
            for (int ir = 0; ir < 6; ir++){
                const uint4* w4 = (const uint4*)&Wn[im*784 + (2*rr + ir)*28 + x0];
                uint4 lo4 = w4[0], hi4 = w4[1];
                unsigned wn[8] = {lo4.x,lo4.y,lo4.z,lo4.w, hi4.x,hi4.y,hi4.z,hi4.w};
                #pragma unroll
                for (int row = 0; row < 2; row++){
                    int ky = ir - row;
                    if (ky >= 0 && ky <= 4){
                        uint4 wlo = *(const uint4*)&wlo_s[ky*20 + cg*4];
                        uint4 whi = *(const uint4*)&whi_s[ky*20 + cg*4];
                        #pragma unroll
                        for (int c = 0; c < 4; c++){
                            unsigned wl = wn[c], wh = wn[c + 4];
                            acc[row][c][0] = __dp4a(wl, wlo.x, acc[row][c][0]);
                            acc[row][c][1] = __dp4a(wl, wlo.y, acc[row][c][1]);
                            acc[row][c][2] = __dp4a(wl, wlo.z, acc[row][c][2]);
                            acc[row][c][3] = __dp4a(wl, wlo.w, acc[row][c][3]);
                            acc[row][c][0] = __dp4a(wh, whi.x, acc[row][c][0]);
                            acc[row][c][1] = __dp4a(wh, whi.y, acc[row][c][1]);
                            acc[row][c][2] = __dp4a(wh, whi.z, acc[row][c][2]);
                            acc[row][c][3] = __dp4a(wh, whi.w, acc[row][c][3]);
                        }
                    }
                }
            }

            int ZP[2][4];
            #pragma unroll
            for (int rw = 0; rw < 2; rw++)
                #pragma unroll
                for (int cl = 0; cl < 4; cl++)
                    ZP[rw][cl] = zpi * (int)Ps[im*576 + (2*rr + rw)*24 + x0 + cl];

            unsigned ow0 = 0u, ow1 = 0u;
            #pragma unroll
            for (int c = 0; c < 4; c++){
                float Cc = cc_s[cg*4 + c];
                #pragma unroll
                for (int px = 0; px < 2; px++){
                    int i0 = (int)acc[0][2*px    ][c] - ZP[0][2*px    ];
                    int i1 = (int)acc[0][2*px + 1][c] - ZP[0][2*px + 1];
                    int i2 = (int)acc[1][2*px    ][c] - ZP[1][2*px    ];
                    int i3 = (int)acc[1][2*px + 1][c] - ZP[1][2*px + 1];
                    int imx = max(max(i0, i1), max(i2, i3));
                    float q = rintf(fmaxf(Af*(float)imx + Cc, 0.0f));
                    unsigned qb = ((unsigned)q & 0xffu) << (8*c);
                    if (px == 0) ow0 |= qb; else ow1 |= qb;
                }
            }
            // channel-packed write straight into conv2's Xs layout
            unsigned* dst = &Xs[im*720 + (rr*5 + cg)*12 + xp*2];
            dst[0] = ow0; dst[1] = ow1;
        }
    }
    __syncthreads();   // conv1 scratch dead; Xs complete

    // ===== conv2 phase (round-8 proven) =====
    for (int i = tid; i < 128*14; i += 256){
        int g = i / 14, c4 = i % 14;
        uint4 v = make_uint4(0u,0u,0u,0u);
        if (g < 125 && c4 < 13){
            int r = g / 5, p = g % 5;
            v = *(const uint4*)&g_w2q[(p*25 + r)*C2_CPAD + c4*4];
        }
        ((uint4*)Bs)[g*14 + c4] = v;
    }
    if (tid < 128){
        int g = tid;
        int r = (g < 125) ? g/5 : 0, p = (g < 125) ? g%5 : 0;
        offA[tid] = (r/5)*60 + p*12 + (r%5);
    }
    if (tid < C2_CPAD) beff_s[tid] = g_b2eff[tid];
    if (tid < 2) rsum[tid] = 0;
    __syncthreads();

    if (tid < 128){
        int li = tid >> 6, pos = tid & 63;
        int oy = pos >> 3, ox = pos & 7;
        unsigned s = 0;
        for (int ky = 0; ky < 5; ky++)
            for (int p = 0; p < 5; p++){
                const unsigned* row = &Xs[li*720 + (oy + ky)*60 + p*12];
                #pragma unroll
                for (int kx = 0; kx < 5; kx++)
                    s = __dp4a(row[ox + kx], 0x01010101u, s);
            }
        Sw[tid] = s;
    }

    int w = tid >> 5, l = tid & 31;
    int li = w >> 2, mtile = w & 3;
    int lr = l >> 2, lc = l & 3;
    int oy0 = mtile*2;
    int base0 = li*720 + oy0*60 + lr;
    int base1 = base0 + 60;

    int acc2[7][4];
    #pragma unroll
    for (int t = 0; t < 7; t++)
        #pragma unroll
        for (int j = 0; j < 4; j++) acc2[t][j] = 0;

    #pragma unroll 1
    for (int step = 0; step < 16; step++){
        int g0 = step*8 + lc;
        int g1 = g0 + 4;
        unsigned a0 = Xs[base0 + offA[g0]];
        unsigned a1 = Xs[base1 + offA[g0]];
        unsigned a2 = Xs[base0 + offA[g1]];
        unsigned a3 = Xs[base1 + offA[g1]];
        const unsigned* b0r = &Bs[g0*56 + lr];
        const unsigned* b1r = &Bs[g1*56 + lr];
        #pragma unroll
        for (int t = 0; t < 7; t++){
            unsigned b0 = b0r[t*8];
            unsigned b1 = b1r[t*8];
            asm volatile(
                "mma.sync.aligned.m16n8k32.row.col.s32.u8.u8.s32 "
                "{%0,%1,%2,%3}, {%4,%5,%6,%7}, {%8,%9}, {%0,%1,%2,%3};"
                : "+r"(acc2[t][0]), "+r"(acc2[t][1]), "+r"(acc2[t][2]), "+r"(acc2[t][3])
                : "r"(a0), "r"(a1), "r"(a2), "r"(a3), "r"(b0), "r"(b1));
        }
    }
    __syncthreads();

    {
        float s2w, z2w; get_sz(2, s2w, z2w);
        float S2s = S2C * s2w;
        int zp2 = (int)z2w;
        #pragma unroll
        for (int half = 0; half < 2; half++){
            int oy = oy0 + half, ox = lr;
            int sw = (int)Sw[li*64 + oy*8 + ox];
            #pragma unroll
            for (int t = 0; t < 7; t++){
                #pragma unroll
                for (int j = 0; j < 2; j++){
                    int ch = t*8 + lc*2 + j;
                    if (ch < C2_CPAD){
                        int cval = acc2[t][half*2 + j];
                        float val = S2s * (float)(cval - zp2*sw) + beff_s[ch];
                        float v = rintf(fmaxf(val * INV_S3, 0.0f));
                        q2[((li*C2_CPAD + ch)*8 + oy)*8 + ox] = (unsigned char)(unsigned)v;
                    }
                }
            }
        }
    }
    __syncthreads();

    // pool 2x2 + per-image rowsum
    int lsum0 = 0, lsum1 = 0;
    for (int i = tid; i < 1600; i += 256){
        int im = i / 800, rest = i % 800;
        int ch = rest / 16, pr = (rest % 16) / 4, pc = rest % 4;
        const unsigned char* bp = q2 + ((im*C2_CPAD + ch)*8 + 2*pr)*8 + 2*pc;
        unsigned char m = max(max(bp[0], bp[1]), max(bp[8], bp[9]));
        g_act2[((imgbase + im)*50 + ch)*16 + pr*4 + pc] = m;
        if (im == 0) lsum0 += m; else lsum1 += m;
    }
    #pragma unroll
    for (int off = 16; off; off >>= 1){
        lsum0 += __shfl_down_sync(0xffffffffu, lsum0, off);
        lsum1 += __shfl_down_sync(0xffffffffu, lsum1, off);
    }
    if ((tid & 31) == 0){
        if (lsum0) atomicAdd(&rsum[0], lsum0);
        if (lsum1) atomicAdd(&rsum[1], lsum1);
    }
    __syncthreads();
    if (tid < 2) g_rowsum[imgbase + tid] = rsum[tid];
}

// ---------------- fc1 via int8 mma + quant; output u8 q-values ----------------
__global__ void __launch_bounds__(256) fc1_kernel(){
    __shared__ unsigned As[64*44];
    __shared__ unsigned Bs[40*72];

    int tid = threadIdx.x;
    int w = tid >> 5, l = tid & 31;
    int lr = l >> 2, lc = l & 3;
    int m0 = blockIdx.x * 64, n0 = blockIdx.y * 64;
    int wm = (w & 1) * 32;
    int wn = (w >> 1) * 16;

    int acc[2][2][4];
    #pragma unroll
    for (int mt = 0; mt < 2; mt++)
        #pragma unroll
        for (int nt = 0; nt < 2; nt++)
            #pragma unroll
            for (int j = 0; j < 4; j++) acc[mt][nt][j] = 0;

    const unsigned* Xg = (const unsigned*)g_act2;

    #pragma unroll 1
    for (int chunk = 0; chunk < 5; chunk++){
        for (int i = tid; i < 640; i += 256){
            int r = i / 10, c4 = i % 10;
            uint4 v = *(const uint4*)&Xg[(m0 + r)*200 + chunk*40 + c4*4];
            *(uint4*)&As[r*44 + c4*4] = v;
        }
        for (int i = tid; i < 640; i += 256){
            int kr = i / 16, c4 = i % 16;
            uint4 v = *(const uint4*)&g_fc1q[(chunk*40 + kr)*512 + n0 + c4*4];
            *(uint4*)&Bs[kr*72 + c4*4] = v;
        }
        __syncthreads();

        #pragma unroll
        for (int s = 0; s < 5; s++){
            int g = s*8;
            unsigned a[2][4];
            #pragma unroll
            for (int mt = 0; mt < 2; mt++){
                int r0 = wm + mt*16 + lr;
                a[mt][0] = As[r0*44 + g + lc];
                a[mt][1] = As[(r0 + 8)*44 + g + lc];
                a[mt][2] = As[r0*44 + g + 4 + lc];
                a[mt][3] = As[(r0 + 8)*44 + g + 4 + lc];
            }
            unsigned b[2][2];
            #pragma unroll
            for (int nt = 0; nt < 2; nt++){
                int nn = wn + nt*8 + lr;
                b[nt][0] = Bs[(g + lc)*72 + nn];
                b[nt][1] = Bs[(g + 4 + lc)*72 + nn];
            }
            #pragma unroll
            for (int mt = 0; mt < 2; mt++)
                #pragma unroll
                for (int nt = 0; nt < 2; nt++){
                    asm volatile(
                        "mma.sync.aligned.m16n8k32.row.col.s32.u8.u8.s32 "
                        "{%0,%1,%2,%3}, {%4,%5,%6,%7}, {%8,%9}, {%0,%1,%2,%3};"
                        : "+r"(acc[mt][nt][0]), "+r"(acc[mt][nt][1]),
                          "+r"(acc[mt][nt][2]), "+r"(acc[mt][nt][3])
                        : "r"(a[mt][0]), "r"(a[mt][1]), "r"(a[mt][2]), "r"(a[mt][3]),
                          "r"(b[nt][0]), "r"(b[nt][1]));
                }
        }
        __syncthreads();
    }

    float s3w, z3w; get_sz(4, s3w, z3w);
    float S3s = S3C * s3w;
    int zp3 = (int)z3w;

    #pragma unroll
    for (int mt = 0; mt < 2; mt++){
        int mr0 = m0 + wm + mt*16 + lr;
        int rs0 = g_rowsum[mr0];
        int rs1 = g_rowsum[mr0 + 8];
        #pragma unroll
        for (int nt = 0; nt < 2; nt++){
            int nb = n0 + wn + nt*8 + 2*lc;
            #pragma unroll
            for (int j = 0; j < 2; j++){
                int n = nb + j;
                if (n < 500){
                    float y0 = S3s * (float)(acc[mt][nt][j]     - zp3 * rs0) + g_b3eff[n];
                    float v0 = rintf(fmaxf(y0 * INV_S4, 0.0f));
                    g_xq[mr0*500 + n] = (unsigned char)((unsigned)v0 & 0xffu);
                    float y1 = S3s * (float)(acc[mt][nt][2 + j] - zp3 * rs1) + g_b3eff[n];
                    float v1 = rintf(fmaxf(y1 * INV_S4, 0.0f));
                    g_xq[(mr0 + 8)*500 + n] = (unsigned char)((unsigned)v1 & 0xffu);
                }
            }
        }
    }
}

// ---------------- fc2 + log_softmax (+ re-arm minmax keys for next run) ----------------
__global__ void __launch_bounds__(128) fc2_kernel(const float* __restrict__ w,
                                                  const float* __restrict__ bias,
                                                  float* __restrict__ out){
    __shared__ float ws[5000];
    __shared__ float bsh[10];
    int tid = threadIdx.x;

    if (blockIdx.x == 0 && tid < 12)
        g_mmkey[tid] = (tid & 1) ? 0u : 0xFFFFFFFFu;

    for (int i = tid; i < 5000; i += 128) ws[i] = w[i];
    if (tid < 10) bsh[tid] = bias[tid];
    __syncthreads();

    int warp = tid / 32, lane = tid % 32;
    int row = blockIdx.x*4 + warp;
    float acc[10];
    #pragma unroll
    for (int j = 0; j < 10; j++) acc[j] = 0.0f;

    for (int k = lane; k < 500; k += 32){
        float xv = S4 * (float)g_xq[row*500 + k];
        #pragma unroll
        for (int j = 0; j < 10; j++) acc[j] += xv * ws[j*500 + k];
    }
    #pragma unroll
    for (int j = 0; j < 10; j++){
        #pragma unroll
        for (int off = 16; off; off >>= 1)
            acc[j] += __shfl_down_sync(0xffffffffu, acc[j], off);
    }
    if (lane == 0){
        float l[10], m = -1e30f;
        #pragma unroll
        for (int j = 0; j < 10; j++){ l[j] = acc[j] + bsh[j]; m = fmaxf(m, l[j]); }
        float s = 0.0f;
        #pragma unroll
        for (int j = 0; j < 10; j++) s += expf(l[j] - m);
        float ls = logf(s);
        #pragma unroll
        for (int j = 0; j < 10; j++) out[row*10 + j] = l[j] - m - ls;
    }
}

// ---------------- launch ----------------
extern "C" void kernel_launch(void* const* d_in, const int* in_sizes, int n_in,
                              void* d_out, int out_size){
    const float* x   = (const float*)d_in[0];
    const float* c1w = (const float*)d_in[1];
    const float* c1b = (const float*)d_in[2];
    const float* c2w = (const float*)d_in[3];
    const float* c2b = (const float*)d_in[4];
    const float* f1w = (const float*)d_in[5];
    const float* f1b = (const float*)d_in[6];
    const float* f2w = (const float*)d_in[7];
    const float* f2b = (const float*)d_in[8];

    minmax_kernel<<<72, 256>>>(c1w, c1b, c2w, c2b, f1w, f1b);
    effs_kernel<<<429, 256>>>(c1w, c1b, c2w, c2b, f1w, f1b);
    convfused_kernel<<<BATCH/2, 256>>>(x);
    fc1_kernel<<<dim3(BATCH/64, 8), 256>>>();
    fc2_kernel<<<BATCH/4, 128>>>(f2w, f2b, (float*)d_out);
}